// round 12
// baseline (speedup 1.0000x reference)
#include <cuda_runtime.h>
#include <cuda_bf16.h>
#include <cstdint>

// DifferentiableTopKSelector == per-row hard top-32 mask of raw scores
// (straight-through estimator is value-identical to hard_mask; `u` is dead).
//
// Round 12: R11 skeleton (NT=512, front-batched LDG.128, inline zero STG.128,
// guess-threshold candidates, exact stable rank on composite keys) with the
// two remaining intra-CTA serializers removed:
//  - warp-aggregated candidate push: 1 shared atomic per warp (was ~70/CTA)
//  - no barrier before the load burst (s_cnt init covered by the pre-atomic
//    barrier instead)

static constexpr int COLS = 8192;
static constexpr int NT   = 512;
static constexpr int VPT  = COLS / 4 / NT;   // 4 float4 per thread
static constexpr int CAP  = 256;
static constexpr int KSEL = 32;
#define GUESS 2.3f

__device__ __forceinline__ unsigned long long pack_key(float v, unsigned idx) {
    // v > GUESS > 0: float bits compare as unsigned. Inverted index makes
    // larger composite == (larger value, then smaller index) — exactly
    // jax.lax.top_k's stable tie-break.
    return ((unsigned long long)__float_as_uint(v) << 32)
         | (unsigned long long)(COLS - 1u - idx);
}

__global__ void __launch_bounds__(NT, 4)
topk_mask_kernel(const float* __restrict__ scores, float* __restrict__ out) {
    __shared__ unsigned long long cand[CAP];   // 2 KB
    __shared__ int s_cnt;

    const int t = threadIdx.x;
    if (t == 0) s_cnt = 0;                     // visible after the 1st barrier

    const size_t rowoff = (size_t)blockIdx.x * (size_t)COLS;
    const float4* in4  = (const float4*)(scores + rowoff);
    float4*       out4 = (float4*)(out + rowoff);
    const float4  zero4 = make_float4(0.f, 0.f, 0.f, 0.f);

    // ---- phase 1: loads issue immediately, back-to-back (no barrier) ----
    float4 v[VPT];
    #pragma unroll
    for (int it = 0; it < VPT; ++it)
        v[it] = __ldcs(in4 + t + it * NT);

    // ---- phase 2: zero fill (independent of load results) ----
    #pragma unroll
    for (int it = 0; it < VPT; ++it)
        __stcs(out4 + t + it * NT, zero4);

    // ---- phase 3: per-lane hit count (registers only) ----
    unsigned n = 0;
    #pragma unroll
    for (int it = 0; it < VPT; ++it)
        n += (v[it].x > GUESS) + (v[it].y > GUESS)
           + (v[it].z > GUESS) + (v[it].w > GUESS);

    __syncthreads();     // orders s_cnt=0 before atomics; nothing else waits

    // ---- phase 4: warp-aggregated push — ONE atomic per warp ----
    unsigned incl = n;
    #pragma unroll
    for (int d = 1; d < 32; d <<= 1) {
        unsigned o = __shfl_up_sync(0xFFFFFFFFu, incl, d);
        if ((t & 31) >= d) incl += o;
    }
    const unsigned total = __shfl_sync(0xFFFFFFFFu, incl, 31);
    if (total) {
        unsigned base = 0;
        if ((t & 31) == 31) base = (unsigned)atomicAdd(&s_cnt, (int)total);
        base = __shfl_sync(0xFFFFFFFFu, base, 31);
        if (n) {
            unsigned pos = base + incl - n;
            #pragma unroll
            for (int it = 0; it < VPT; ++it) {
                const unsigned bb = (unsigned)((t + it * NT) * 4);
                if (v[it].x > GUESS && pos < CAP) cand[pos++] = pack_key(v[it].x, bb + 0u);
                if (v[it].y > GUESS && pos < CAP) cand[pos++] = pack_key(v[it].y, bb + 1u);
                if (v[it].z > GUESS && pos < CAP) cand[pos++] = pack_key(v[it].z, bb + 2u);
                if (v[it].w > GUESS && pos < CAP) cand[pos++] = pack_key(v[it].w, bb + 3u);
            }
        }
    }
    __syncthreads();

    const int cnt = s_cnt;

    if (cnt >= KSEL && cnt <= CAP) {
        // ---- exact stable rank among candidates; scatter the 32 ones ----
        if (t < cnt) {
            const unsigned long long ci = cand[t];
            int r = 0;
            #pragma unroll 4
            for (int j = 0; j < cnt; ++j)
                r += (cand[j] > ci);                 // LDS.64 broadcast
            if (r < KSEL) {
                unsigned idx = COLS - 1u - (unsigned)(ci & 0xFFFFFFFFull);
                out[rowoff + idx] = 1.0f;
            }
        }
    } else if (t == 0) {
        // ---- exact serial fallback (correctness guard; 6-sigma event) ----
        float    bk[KSEL];
        unsigned bi[KSEL];
        #pragma unroll
        for (int i = 0; i < KSEL; ++i) { bk[i] = -INFINITY; bi[i] = 0u; }
        const float* rowp = scores + rowoff;
        for (int i = 0; i < COLS; ++i) {
            float vv = rowp[i];
            if (vv > bk[KSEL - 1]) {                 // strict > == stable
                int p = KSEL - 1;
                while (p > 0 && vv > bk[p - 1]) {
                    bk[p] = bk[p - 1]; bi[p] = bi[p - 1]; --p;
                }
                bk[p] = vv; bi[p] = (unsigned)i;
            }
        }
        for (int i = 0; i < KSEL; ++i)
            out[rowoff + bi[i]] = 1.0f;
    }
}

extern "C" void kernel_launch(void* const* d_in, const int* in_sizes, int n_in,
                              void* d_out, int out_size) {
    const float* scores = (const float*)d_in[0];   // (4096, 8192) fp32
    // d_in[1] (u) is mathematically dead: output == hard top-k mask of scores.
    float* out = (float*)d_out;
    const int rows = out_size / COLS;              // 4096
    topk_mask_kernel<<<rows, NT>>>(scores, out);
}